// round 1
// baseline (speedup 1.0000x reference)
#include <cuda_runtime.h>

#define THREADS 256
#define ROWS_PER_BLOCK 256
#define IN_F 18
#define OUT_F 7
#define IN_PAD 19   // gcd(19,32)=1 -> conflict-free per-row smem reads
#define OUT_PAD 9   // gcd(9,32)=1

__device__ __forceinline__ float frelu(float v) { return v > 0.f ? v : 0.f; }

__global__ __launch_bounds__(THREADS)
void policy_kernel(const float* __restrict__ x,
                   const float* __restrict__ fc_obs_w, const float* __restrict__ fc_obs_b,
                   const float* __restrict__ fc_emb_w, const float* __restrict__ fc_emb_b,
                   const float* __restrict__ conv1_w,  const float* __restrict__ conv1_b,
                   const float* __restrict__ conv2_w,  const float* __restrict__ conv2_b,
                   const float* __restrict__ deconv1_w, const float* __restrict__ deconv1_b,
                   const float* __restrict__ deconv2_w, const float* __restrict__ deconv2_b,
                   float* __restrict__ out, int n_rows)
{
    __shared__ float s_in[ROWS_PER_BLOCK * IN_PAD];
    __shared__ float s_out[ROWS_PER_BLOCK * OUT_PAD];
    __shared__ float P[33];

    const int tid  = threadIdx.x;
    const int row0 = blockIdx.x * ROWS_PER_BLOCK;
    const int rows = min(ROWS_PER_BLOCK, n_rows - row0);

    // ---- stage params into smem (one small array per thread) ----
    if (tid < 12) {
        switch (tid) {
            case 0:  for (int i = 0; i < 8; i++) P[0 + i]  = fc_obs_w[i];  break;
            case 1:  for (int i = 0; i < 2; i++) P[8 + i]  = fc_obs_b[i];  break;
            case 2:  for (int i = 0; i < 4; i++) P[10 + i] = fc_emb_w[i];  break;
            case 3:  for (int i = 0; i < 2; i++) P[14 + i] = fc_emb_b[i];  break;
            case 4:  for (int i = 0; i < 6; i++) P[16 + i] = conv1_w[i];   break;
            case 5:  P[22] = conv1_b[0];                                   break;
            case 6:  for (int i = 0; i < 2; i++) P[23 + i] = conv2_w[i];   break;
            case 7:  P[25] = conv2_b[0];                                   break;
            case 8:  for (int i = 0; i < 2; i++) P[26 + i] = deconv1_w[i]; break;
            case 9:  P[28] = deconv1_b[0];                                 break;
            case 10: for (int i = 0; i < 3; i++) P[29 + i] = deconv2_w[i]; break;
            case 11: P[32] = deconv2_b[0];                                 break;
        }
    }

    // ---- stage input: fully coalesced global reads -> padded smem rows ----
    const int total_in = rows * IN_F;
    const float* gin = x + (size_t)row0 * IN_F;
    for (int i = tid; i < total_in; i += THREADS) {
        int r = i / IN_F;
        int c = i - r * IN_F;
        s_in[r * IN_PAD + c] = gin[i];
    }
    __syncthreads();

    // ---- per-row compute ----
    if (tid < rows) {
        const float* r = &s_in[tid * IN_PAD];
        // obs = r[0..3], j = r[4..10], jd = r[11..17]

        // fc_obs: relu(obs @ W.T + b), W (2,4) row-major
        float fo0 = frelu(r[0]*P[0] + r[1]*P[1] + r[2]*P[2] + r[3]*P[3] + P[8]);
        float fo1 = frelu(r[0]*P[4] + r[1]*P[5] + r[2]*P[6] + r[3]*P[7] + P[9]);

        // conv1: OIH (1,2,3), stride 2, VALID over length 7 -> 3 outputs
        // y1[t] = relu( sum_h j[2t+h]*w[0,0,h] + jd[2t+h]*w[0,1,h] + b )
        float y1[3];
        #pragma unroll
        for (int t = 0; t < 3; t++) {
            int b = 2 * t;
            y1[t] = frelu(r[4  + b]*P[16] + r[5  + b]*P[17] + r[6  + b]*P[18]
                        + r[11 + b]*P[19] + r[12 + b]*P[20] + r[13 + b]*P[21]
                        + P[22]);
        }

        // conv2: (1,1,2), stride 1 -> 2 outputs
        float y2_0 = frelu(y1[0]*P[23] + y1[1]*P[24] + P[25]);
        float y2_1 = frelu(y1[1]*P[23] + y1[2]*P[24] + P[25]);

        // fc_emb: relu((fc_obs + fm) @ We.T + be), We (2,2) row-major
        float ein0 = fo0 + y2_0;
        float ein1 = fo1 + y2_1;
        float e0 = frelu(ein0*P[10] + ein1*P[11] + P[14]);
        float e1 = frelu(ein0*P[12] + ein1*P[13] + P[15]);

        // deconv1 = adjoint of conv(stride1, k=2): out[p] = sum_{t+h=p} e[t]*w[h]
        float d0 = frelu(e0*P[26]            + P[28]);
        float d1 = frelu(e0*P[27] + e1*P[26] + P[28]);
        float d2 = frelu(e1*P[27]            + P[28]);

        // deconv2 = adjoint of conv(stride2, k=3): out[p] = sum_{2t+h=p} d[t]*w[h]
        float* o = &s_out[tid * OUT_PAD];
        o[0] = d0*P[29]            + P[32];
        o[1] = d0*P[30]            + P[32];
        o[2] = d0*P[31] + d1*P[29] + P[32];
        o[3] = d1*P[30]            + P[32];
        o[4] = d1*P[31] + d2*P[29] + P[32];
        o[5] = d2*P[30]            + P[32];
        o[6] = d2*P[31]            + P[32];
    }
    __syncthreads();

    // ---- stage output: padded smem rows -> fully coalesced global writes ----
    const int total_out = rows * OUT_F;
    float* gout = out + (size_t)row0 * OUT_F;
    for (int i = tid; i < total_out; i += THREADS) {
        int r = i / OUT_F;
        int c = i - r * OUT_F;
        gout[i] = s_out[r * OUT_PAD + c];
    }
}

extern "C" void kernel_launch(void* const* d_in, const int* in_sizes, int n_in,
                              void* d_out, int out_size) {
    const float* x          = (const float*)d_in[0];
    const float* fc_obs_w   = (const float*)d_in[1];
    const float* fc_obs_b   = (const float*)d_in[2];
    const float* fc_emb_w   = (const float*)d_in[3];
    const float* fc_emb_b   = (const float*)d_in[4];
    const float* conv1_w    = (const float*)d_in[5];
    const float* conv1_b    = (const float*)d_in[6];
    const float* conv2_w    = (const float*)d_in[7];
    const float* conv2_b    = (const float*)d_in[8];
    const float* deconv1_w  = (const float*)d_in[9];
    const float* deconv1_b  = (const float*)d_in[10];
    const float* deconv2_w  = (const float*)d_in[11];
    const float* deconv2_b  = (const float*)d_in[12];
    float* out = (float*)d_out;

    int n_rows = in_sizes[0] / IN_F;
    int grid = (n_rows + ROWS_PER_BLOCK - 1) / ROWS_PER_BLOCK;

    policy_kernel<<<grid, THREADS>>>(x,
        fc_obs_w, fc_obs_b, fc_emb_w, fc_emb_b,
        conv1_w, conv1_b, conv2_w, conv2_b,
        deconv1_w, deconv1_b, deconv2_w, deconv2_b,
        out, n_rows);
}

// round 2
// speedup vs baseline: 1.3064x; 1.3064x over previous
#include <cuda_runtime.h>

#define THREADS 256
#define ROWS_PER_BLOCK 256
#define IN_F 18
#define OUT_F 7

__device__ __forceinline__ float frelu(float v) { return v > 0.f ? v : 0.f; }

__global__ __launch_bounds__(THREADS)
void policy_kernel(const float* __restrict__ x,
                   const float* __restrict__ fc_obs_w, const float* __restrict__ fc_obs_b,
                   const float* __restrict__ fc_emb_w, const float* __restrict__ fc_emb_b,
                   const float* __restrict__ conv1_w,  const float* __restrict__ conv1_b,
                   const float* __restrict__ conv2_w,  const float* __restrict__ conv2_b,
                   const float* __restrict__ deconv1_w, const float* __restrict__ deconv1_b,
                   const float* __restrict__ deconv2_w, const float* __restrict__ deconv2_b,
                   float* __restrict__ out, int n_rows)
{
    __shared__ float s_in[ROWS_PER_BLOCK * IN_F];    // linear, unpadded -> pure vec copy
    __shared__ float s_out[ROWS_PER_BLOCK * OUT_F];  // linear, unpadded
    __shared__ float P[33];

    const int tid  = threadIdx.x;
    const int row0 = blockIdx.x * ROWS_PER_BLOCK;
    const int rows = min(ROWS_PER_BLOCK, n_rows - row0);

    // ---- stage params into smem ----
    if (tid < 12) {
        switch (tid) {
            case 0:  for (int i = 0; i < 8; i++) P[0 + i]  = fc_obs_w[i];  break;
            case 1:  for (int i = 0; i < 2; i++) P[8 + i]  = fc_obs_b[i];  break;
            case 2:  for (int i = 0; i < 4; i++) P[10 + i] = fc_emb_w[i];  break;
            case 3:  for (int i = 0; i < 2; i++) P[14 + i] = fc_emb_b[i];  break;
            case 4:  for (int i = 0; i < 6; i++) P[16 + i] = conv1_w[i];   break;
            case 5:  P[22] = conv1_b[0];                                   break;
            case 6:  for (int i = 0; i < 2; i++) P[23 + i] = conv2_w[i];   break;
            case 7:  P[25] = conv2_b[0];                                   break;
            case 8:  for (int i = 0; i < 2; i++) P[26 + i] = deconv1_w[i]; break;
            case 9:  P[28] = deconv1_b[0];                                 break;
            case 10: for (int i = 0; i < 3; i++) P[29 + i] = deconv2_w[i]; break;
            case 11: P[32] = deconv2_b[0];                                 break;
        }
    }

    // ---- stage input: vectorized linear copy (no index math) ----
    const int total_in = rows * IN_F;
    const float* gin = x + (size_t)row0 * IN_F;        // 16B-aligned (row0*72 bytes)
    const float4* gin4 = (const float4*)gin;
    float4* sin4 = (float4*)s_in;
    const int nvec_in = total_in >> 2;
    for (int i = tid; i < nvec_in; i += THREADS) sin4[i] = gin4[i];
    for (int i = (nvec_in << 2) + tid; i < total_in; i += THREADS) s_in[i] = gin[i];
    __syncthreads();

    // ---- per-row compute ----
    if (tid < rows) {
        float r[IN_F];
        const float2* rp = (const float2*)(s_in + tid * IN_F);  // tid*72B: 8B-aligned
        #pragma unroll
        for (int i = 0; i < 9; i++) { float2 t = rp[i]; r[2*i] = t.x; r[2*i+1] = t.y; }

        // fc_obs
        float fo0 = frelu(r[0]*P[0] + r[1]*P[1] + r[2]*P[2] + r[3]*P[3] + P[8]);
        float fo1 = frelu(r[0]*P[4] + r[1]*P[5] + r[2]*P[6] + r[3]*P[7] + P[9]);

        // conv1 (2,3) stride 2 over len 7 -> 3
        float y1[3];
        #pragma unroll
        for (int t = 0; t < 3; t++) {
            int b = 2 * t;
            y1[t] = frelu(r[4  + b]*P[16] + r[5  + b]*P[17] + r[6  + b]*P[18]
                        + r[11 + b]*P[19] + r[12 + b]*P[20] + r[13 + b]*P[21]
                        + P[22]);
        }

        // conv2 (1,2) stride 1 -> 2
        float y2_0 = frelu(y1[0]*P[23] + y1[1]*P[24] + P[25]);
        float y2_1 = frelu(y1[1]*P[23] + y1[2]*P[24] + P[25]);

        // fc_emb
        float ein0 = fo0 + y2_0;
        float ein1 = fo1 + y2_1;
        float e0 = frelu(ein0*P[10] + ein1*P[11] + P[14]);
        float e1 = frelu(ein0*P[12] + ein1*P[13] + P[15]);

        // deconv1 (k=2, s=1) adjoint -> 3
        float d0 = frelu(e0*P[26]            + P[28]);
        float d1 = frelu(e0*P[27] + e1*P[26] + P[28]);
        float d2 = frelu(e1*P[27]            + P[28]);

        // deconv2 (k=3, s=2) adjoint -> 7
        float* o = &s_out[tid * OUT_F];   // stride 7: conflict-free
        o[0] = d0*P[29]            + P[32];
        o[1] = d0*P[30]            + P[32];
        o[2] = d0*P[31] + d1*P[29] + P[32];
        o[3] = d1*P[30]            + P[32];
        o[4] = d1*P[31] + d2*P[29] + P[32];
        o[5] = d2*P[30]            + P[32];
        o[6] = d2*P[31]            + P[32];
    }
    __syncthreads();

    // ---- stage output: vectorized linear copy ----
    const int total_out = rows * OUT_F;
    float* gout = out + (size_t)row0 * OUT_F;          // 16B-aligned (row0*28 bytes)
    const float4* sout4 = (const float4*)s_out;
    float4* gout4 = (float4*)gout;
    const int nvec_out = total_out >> 2;
    for (int i = tid; i < nvec_out; i += THREADS) gout4[i] = sout4[i];
    for (int i = (nvec_out << 2) + tid; i < total_out; i += THREADS) gout[i] = s_out[i];
}

extern "C" void kernel_launch(void* const* d_in, const int* in_sizes, int n_in,
                              void* d_out, int out_size) {
    const float* x          = (const float*)d_in[0];
    const float* fc_obs_w   = (const float*)d_in[1];
    const float* fc_obs_b   = (const float*)d_in[2];
    const float* fc_emb_w   = (const float*)d_in[3];
    const float* fc_emb_b   = (const float*)d_in[4];
    const float* conv1_w    = (const float*)d_in[5];
    const float* conv1_b    = (const float*)d_in[6];
    const float* conv2_w    = (const float*)d_in[7];
    const float* conv2_b    = (const float*)d_in[8];
    const float* deconv1_w  = (const float*)d_in[9];
    const float* deconv1_b  = (const float*)d_in[10];
    const float* deconv2_w  = (const float*)d_in[11];
    const float* deconv2_b  = (const float*)d_in[12];
    float* out = (float*)d_out;

    int n_rows = in_sizes[0] / IN_F;
    int grid = (n_rows + ROWS_PER_BLOCK - 1) / ROWS_PER_BLOCK;

    policy_kernel<<<grid, THREADS>>>(x,
        fc_obs_w, fc_obs_b, fc_emb_w, fc_emb_b,
        conv1_w, conv1_b, conv2_w, conv2_b,
        deconv1_w, deconv1_b, deconv2_w, deconv2_b,
        out, n_rows);
}

// round 3
// speedup vs baseline: 1.5750x; 1.2056x over previous
#include <cuda_runtime.h>
#include <cstdint>

#define THREADS 256
#define RPB 256
#define IN_F 18
#define OUT_F 7

__device__ __forceinline__ float frelu(float v) { return v > 0.f ? v : 0.f; }
__device__ __forceinline__ unsigned smem_addr(const void* p) {
    return (unsigned)__cvta_generic_to_shared(p);
}

__global__ __launch_bounds__(THREADS)
void policy_kernel(const float* __restrict__ x,
                   const float* __restrict__ fc_obs_w, const float* __restrict__ fc_obs_b,
                   const float* __restrict__ fc_emb_w, const float* __restrict__ fc_emb_b,
                   const float* __restrict__ conv1_w,  const float* __restrict__ conv1_b,
                   const float* __restrict__ conv2_w,  const float* __restrict__ conv2_b,
                   const float* __restrict__ deconv1_w, const float* __restrict__ deconv1_b,
                   const float* __restrict__ deconv2_w, const float* __restrict__ deconv2_b,
                   float* __restrict__ out, int n_rows)
{
    __shared__ __align__(16) float s_in[RPB * IN_F];
    __shared__ __align__(16) float s_out[RPB * OUT_F];
    __shared__ float P[33];
    __shared__ __align__(8) unsigned long long mbar;

    const int tid  = threadIdx.x;
    const int row0 = blockIdx.x * RPB;
    const int rows = min(RPB, n_rows - row0);
    const bool full = (rows == RPB);

    // ---- params into smem ----
    if (tid < 12) {
        switch (tid) {
            case 0:  for (int i = 0; i < 8; i++) P[0 + i]  = fc_obs_w[i];  break;
            case 1:  for (int i = 0; i < 2; i++) P[8 + i]  = fc_obs_b[i];  break;
            case 2:  for (int i = 0; i < 4; i++) P[10 + i] = fc_emb_w[i];  break;
            case 3:  for (int i = 0; i < 2; i++) P[14 + i] = fc_emb_b[i];  break;
            case 4:  for (int i = 0; i < 6; i++) P[16 + i] = conv1_w[i];   break;
            case 5:  P[22] = conv1_b[0];                                   break;
            case 6:  for (int i = 0; i < 2; i++) P[23 + i] = conv2_w[i];   break;
            case 7:  P[25] = conv2_b[0];                                   break;
            case 8:  for (int i = 0; i < 2; i++) P[26 + i] = deconv1_w[i]; break;
            case 9:  P[28] = deconv1_b[0];                                 break;
            case 10: for (int i = 0; i < 3; i++) P[29 + i] = deconv2_w[i]; break;
            case 11: P[32] = deconv2_b[0];                                 break;
        }
    }

    const float* gin = x + (size_t)row0 * IN_F;

    if (full) {
        if (tid == 0) {
            unsigned mb = smem_addr(&mbar);
            asm volatile("mbarrier.init.shared::cta.b64 [%0], 1;" :: "r"(mb) : "memory");
        }
        __syncthreads();   // orders mbarrier init + param STS
        if (tid == 0) {
            unsigned mb = smem_addr(&mbar);
            unsigned dst = smem_addr(s_in);
            const unsigned bytes = RPB * IN_F * 4;  // 18432, mult of 16
            asm volatile("mbarrier.arrive.expect_tx.shared::cta.b64 _, [%0], %1;"
                         :: "r"(mb), "r"(bytes) : "memory");
            asm volatile("cp.async.bulk.shared::cta.global.mbarrier::complete_tx::bytes "
                         "[%0], [%1], %2, [%3];"
                         :: "r"(dst), "l"(gin), "r"(bytes), "r"(mb) : "memory");
        }
        // all threads wait for TMA completion (phase 0)
        {
            unsigned mb = smem_addr(&mbar);
            asm volatile(
                "{\n\t.reg .pred p;\n\t"
                "WL%=:\n\t"
                "mbarrier.try_wait.parity.acquire.cta.shared::cta.b64 p, [%0], 0;\n\t"
                "@!p bra WL%=;\n\t}"
                :: "r"(mb) : "memory");
        }
    } else {
        // tail block: plain vectorized staging
        const int total_in = rows * IN_F;
        const float4* gin4 = (const float4*)gin;
        float4* sin4 = (float4*)s_in;
        const int nvec = total_in >> 2;
        for (int i = tid; i < nvec; i += THREADS) sin4[i] = gin4[i];
        for (int i = (nvec << 2) + tid; i < total_in; i += THREADS) s_in[i] = gin[i];
        __syncthreads();
    }

    // ---- per-row compute ----
    if (tid < rows) {
        float r[IN_F];
        const float2* rp = (const float2*)(s_in + tid * IN_F);
        #pragma unroll
        for (int i = 0; i < 9; i++) { float2 t = rp[i]; r[2*i] = t.x; r[2*i+1] = t.y; }

        float fo0 = frelu(r[0]*P[0] + r[1]*P[1] + r[2]*P[2] + r[3]*P[3] + P[8]);
        float fo1 = frelu(r[0]*P[4] + r[1]*P[5] + r[2]*P[6] + r[3]*P[7] + P[9]);

        float y1[3];
        #pragma unroll
        for (int t = 0; t < 3; t++) {
            int b = 2 * t;
            y1[t] = frelu(r[4  + b]*P[16] + r[5  + b]*P[17] + r[6  + b]*P[18]
                        + r[11 + b]*P[19] + r[12 + b]*P[20] + r[13 + b]*P[21]
                        + P[22]);
        }

        float y2_0 = frelu(y1[0]*P[23] + y1[1]*P[24] + P[25]);
        float y2_1 = frelu(y1[1]*P[23] + y1[2]*P[24] + P[25]);

        float ein0 = fo0 + y2_0;
        float ein1 = fo1 + y2_1;
        float e0 = frelu(ein0*P[10] + ein1*P[11] + P[14]);
        float e1 = frelu(ein0*P[12] + ein1*P[13] + P[15]);

        float d0 = frelu(e0*P[26]            + P[28]);
        float d1 = frelu(e0*P[27] + e1*P[26] + P[28]);
        float d2 = frelu(e1*P[27]            + P[28]);

        float* o = &s_out[tid * OUT_F];   // stride 7: conflict-free
        o[0] = d0*P[29]            + P[32];
        o[1] = d0*P[30]            + P[32];
        o[2] = d0*P[31] + d1*P[29] + P[32];
        o[3] = d1*P[30]            + P[32];
        o[4] = d1*P[31] + d2*P[29] + P[32];
        o[5] = d2*P[30]            + P[32];
        o[6] = d2*P[31]            + P[32];
    }
    __syncthreads();

    float* gout = out + (size_t)row0 * OUT_F;
    if (full) {
        if (tid == 0) {
            unsigned src = smem_addr(s_out);
            const unsigned bytes = RPB * OUT_F * 4;  // 7168, mult of 16
            asm volatile("fence.proxy.async.shared::cta;" ::: "memory");
            asm volatile("cp.async.bulk.global.shared::cta.bulk_group [%0], [%1], %2;"
                         :: "l"(gout), "r"(src), "r"(bytes) : "memory");
            asm volatile("cp.async.bulk.commit_group;" ::: "memory");
            asm volatile("cp.async.bulk.wait_group.read 0;" ::: "memory");
        }
    } else {
        const int total_out = rows * OUT_F;
        const float4* sout4 = (const float4*)s_out;
        float4* gout4 = (float4*)gout;
        const int nvec = total_out >> 2;
        for (int i = tid; i < nvec; i += THREADS) gout4[i] = sout4[i];
        for (int i = (nvec << 2) + tid; i < total_out; i += THREADS) gout[i] = s_out[i];
    }
}

extern "C" void kernel_launch(void* const* d_in, const int* in_sizes, int n_in,
                              void* d_out, int out_size) {
    const float* x          = (const float*)d_in[0];
    const float* fc_obs_w   = (const float*)d_in[1];
    const float* fc_obs_b   = (const float*)d_in[2];
    const float* fc_emb_w   = (const float*)d_in[3];
    const float* fc_emb_b   = (const float*)d_in[4];
    const float* conv1_w    = (const float*)d_in[5];
    const float* conv1_b    = (const float*)d_in[6];
    const float* conv2_w    = (const float*)d_in[7];
    const float* conv2_b    = (const float*)d_in[8];
    const float* deconv1_w  = (const float*)d_in[9];
    const float* deconv1_b  = (const float*)d_in[10];
    const float* deconv2_w  = (const float*)d_in[11];
    const float* deconv2_b  = (const float*)d_in[12];
    float* out = (float*)d_out;

    int n_rows = in_sizes[0] / IN_F;
    int grid = (n_rows + RPB - 1) / RPB;

    policy_kernel<<<grid, THREADS>>>(x,
        fc_obs_w, fc_obs_b, fc_emb_w, fc_emb_b,
        conv1_w, conv1_b, conv2_w, conv2_b,
        deconv1_w, deconv1_b, deconv2_w, deconv2_b,
        out, n_rows);
}